// round 1
// baseline (speedup 1.0000x reference)
#include <cuda_runtime.h>

#define D   128
#define MAXN 50000
#define TM  64

// ---- scratch (no allocations allowed) ----
__device__ float g_dinv[MAXN];                  // deg -> dinv in place
__device__ float g_h[(size_t)MAXN * D];         // GEMM output (h1, then h2)
__device__ float g_agg[(size_t)MAXN * D];       // conv1 aggregation / BN input
__device__ float g_bnsums[2 * D];               // per-feature sum, sumsq

// ---------------- init: deg=1 (self loop), zero BN accumulators ----------------
__global__ void init_kernel(int n) {
    int i = blockIdx.x * blockDim.x + threadIdx.x;
    if (i < n) g_dinv[i] = 1.0f;
    if (i < 2 * D) g_bnsums[i] = 0.0f;
}

// ---------------- degree accumulation over edge destinations ----------------
__global__ void deg_kernel(const int* __restrict__ dst, int E) {
    int e = blockIdx.x * blockDim.x + threadIdx.x;
    if (e < E) atomicAdd(&g_dinv[dst[e]], 1.0f);
}

__global__ void rsqrt_kernel(int n) {
    int i = blockIdx.x * blockDim.x + threadIdx.x;
    if (i < n) g_dinv[i] = rsqrtf(g_dinv[i]);
}

// ---------------- GEMM: H = X @ W  (optionally BN+ReLU applied to X on load)
// Epilogue: Hout = H ;  Aout = H * dinv[row]^2 + bias   (self-loop + bias init)
__global__ __launch_bounds__(256) void gemm_kernel(
    const float* __restrict__ X, const float* __restrict__ W,
    const float* __restrict__ bias,
    float* __restrict__ Hout, float* __restrict__ Aout,
    int n, int use_bn,
    const float* __restrict__ gamma, const float* __restrict__ beta,
    float invN)
{
    extern __shared__ float sm[];
    float* Ws      = sm;                 // 128*128
    float* Xs      = sm + D * D;         // 64*128
    float* scale_s = Xs + TM * D;        // 128
    float* shift_s = scale_s + D;        // 128

    int tid = threadIdx.x;
    int tx = tid & 31;      // column group (4 cols)
    int ty = tid >> 5;      // row group (8 rows)

    if (use_bn && tid < D) {
        float mu  = g_bnsums[tid] * invN;
        float var = g_bnsums[D + tid] * invN - mu * mu;
        float sc  = gamma[tid] * rsqrtf(var + 1e-5f);
        scale_s[tid] = sc;
        shift_s[tid] = beta[tid] - mu * sc;
    }

    // stage W (16384 floats = 4096 float4)
    const float4* W4 = (const float4*)W;
    float4* Ws4 = (float4*)Ws;
#pragma unroll
    for (int i = 0; i < 16; i++) Ws4[tid + i * 256] = W4[tid + i * 256];
    __syncthreads();

    // stage X tile (64 rows x 128 cols = 2048 float4), applying BN+ReLU if asked
    int row0 = blockIdx.x * TM;
    float4* Xs4 = (float4*)Xs;
#pragma unroll
    for (int i = 0; i < 8; i++) {
        int idx = tid + i * 256;        // 0..2047
        int r   = idx >> 5;
        int c4  = idx & 31;
        int grow = row0 + r;
        float4 v = make_float4(0.f, 0.f, 0.f, 0.f);
        if (grow < n) v = ((const float4*)X)[(size_t)grow * 32 + c4];
        if (use_bn) {
            int f = c4 * 4;
            v.x = fmaxf(0.f, fmaf(v.x, scale_s[f + 0], shift_s[f + 0]));
            v.y = fmaxf(0.f, fmaf(v.y, scale_s[f + 1], shift_s[f + 1]));
            v.z = fmaxf(0.f, fmaf(v.z, scale_s[f + 2], shift_s[f + 2]));
            v.w = fmaxf(0.f, fmaf(v.w, scale_s[f + 3], shift_s[f + 3]));
        }
        Xs4[idx] = v;
    }
    __syncthreads();

    float acc[8][4];
#pragma unroll
    for (int r = 0; r < 8; r++)
#pragma unroll
        for (int c = 0; c < 4; c++) acc[r][c] = 0.f;

#pragma unroll 4
    for (int k = 0; k < D; k++) {
        float4 b = ((const float4*)(Ws + k * D))[tx];
#pragma unroll
        for (int r = 0; r < 8; r++) {
            float a = Xs[(ty * 8 + r) * D + k];   // broadcast within warp
            acc[r][0] = fmaf(a, b.x, acc[r][0]);
            acc[r][1] = fmaf(a, b.y, acc[r][1]);
            acc[r][2] = fmaf(a, b.z, acc[r][2]);
            acc[r][3] = fmaf(a, b.w, acc[r][3]);
        }
    }

    float4 bv = ((const float4*)bias)[tx];
#pragma unroll
    for (int r = 0; r < 8; r++) {
        int grow = row0 + ty * 8 + r;
        if (grow >= n) continue;
        float dv = g_dinv[grow];
        float sl = dv * dv;
        size_t base = (size_t)grow * D + tx * 4;
        float4 h = make_float4(acc[r][0], acc[r][1], acc[r][2], acc[r][3]);
        *(float4*)(Hout + base) = h;
        float4 a2;
        a2.x = fmaf(h.x, sl, bv.x);
        a2.y = fmaf(h.y, sl, bv.y);
        a2.z = fmaf(h.z, sl, bv.z);
        a2.w = fmaf(h.w, sl, bv.w);
        *(float4*)(Aout + base) = a2;
    }
}

// ---------------- edge scatter: out[dst] += h[src] * dinv[src]*dinv[dst]
// one warp per edge; float4 gather + vectorized red.global.add.v4.f32
__global__ __launch_bounds__(256) void scatter_kernel(
    const int* __restrict__ src, const int* __restrict__ dst,
    const float* __restrict__ h, float* __restrict__ out, int E)
{
    int warp = (blockIdx.x * blockDim.x + threadIdx.x) >> 5;
    int lane = threadIdx.x & 31;
    if (warp >= E) return;
    int s = 0, d = 0;
    if (lane == 0) { s = src[warp]; d = dst[warp]; }
    s = __shfl_sync(0xffffffffu, s, 0);
    d = __shfl_sync(0xffffffffu, d, 0);
    float nrm = g_dinv[s] * g_dinv[d];
    float4 v = *(const float4*)(h + (size_t)s * D + lane * 4);
    float* p = out + (size_t)d * D + lane * 4;
    asm volatile("red.global.add.v4.f32 [%0], {%1, %2, %3, %4};"
                 :: "l"(p), "f"(v.x * nrm), "f"(v.y * nrm),
                    "f"(v.z * nrm), "f"(v.w * nrm)
                 : "memory");
}

// ---------------- BN statistics: per-feature sum & sum of squares ----------------
__global__ __launch_bounds__(512) void bnstat_kernel(const float* __restrict__ agg, int n) {
    int f = threadIdx.x & (D - 1);
    int g = threadIdx.x >> 7;                 // 0..3
    int r0 = blockIdx.x * 512 + g;
    int rend = min(n, (int)(blockIdx.x * 512 + 512));
    float s = 0.f, s2 = 0.f;
    for (int r = r0; r < rend; r += 4) {
        float v = agg[(size_t)r * D + f];
        s += v;
        s2 = fmaf(v, v, s2);
    }
    atomicAdd(&g_bnsums[f], s);
    atomicAdd(&g_bnsums[D + f], s2);
}

extern "C" void kernel_launch(void* const* d_in, const int* in_sizes, int n_in,
                              void* d_out, int out_size)
{
    const float* x     = (const float*)d_in[0];
    const int*   ei    = (const int*)  d_in[1];
    const float* W1    = (const float*)d_in[2];
    const float* b1    = (const float*)d_in[3];
    const float* gamma = (const float*)d_in[4];
    const float* beta  = (const float*)d_in[5];
    const float* W2    = (const float*)d_in[6];
    const float* b2    = (const float*)d_in[7];
    float* out = (float*)d_out;

    int n = in_sizes[0] / D;
    int E = in_sizes[1] / 2;
    const int* src = ei;
    const int* dst = ei + E;
    float invN = 1.0f / (float)n;

    int smem = (D * D + TM * D + 2 * D) * (int)sizeof(float);  // 99328 B
    cudaFuncSetAttribute(gemm_kernel,
                         cudaFuncAttributeMaxDynamicSharedMemorySize, smem);

    void* p;
    cudaGetSymbolAddress(&p, g_h);   float* hbuf  = (float*)p;
    cudaGetSymbolAddress(&p, g_agg); float* aggbuf = (float*)p;

    int initThreads = (n > 2 * D) ? n : 2 * D;
    init_kernel<<<(initThreads + 255) / 256, 256>>>(n);
    deg_kernel<<<(E + 255) / 256, 256>>>(dst, E);
    rsqrt_kernel<<<(n + 255) / 256, 256>>>(n);

    int gblocks = (n + TM - 1) / TM;

    // conv1: h1 = x@W1 ; agg1 = h1*dinv^2 + b1 ; then edge scatter
    gemm_kernel<<<gblocks, 256, smem>>>(x, W1, b1, hbuf, aggbuf, n, 0,
                                        nullptr, nullptr, invN);
    long long tw = (long long)E * 32;
    scatter_kernel<<<(int)((tw + 255) / 256), 256>>>(src, dst, hbuf, aggbuf, E);

    // BN stats over agg1
    bnstat_kernel<<<(n + 511) / 512, 512>>>(aggbuf, n);

    // conv2: h2 = BNReLU(agg1)@W2 ; out = h2*dinv^2 + b2 ; then edge scatter
    gemm_kernel<<<gblocks, 256, smem>>>(aggbuf, W2, b2, hbuf, out, n, 1,
                                        gamma, beta, invN);
    scatter_kernel<<<(int)((tw + 255) / 256), 256>>>(src, dst, hbuf, out, E);
}

// round 2
// speedup vs baseline: 1.4811x; 1.4811x over previous
#include <cuda_runtime.h>

#define D    128
#define TM   64
#define MAXN 50048
#define MAXE 1000000
#define NBLK ((MAXN + 255) / 256)

// ---- scratch (no allocations allowed) ----
__device__ float g_dinv[MAXN];
__device__ int   g_deg[MAXN];
__device__ int   g_rowptr[MAXN];
__device__ int   g_cursor[MAXN];
__device__ int   g_csr[MAXE];
__device__ float g_h[(size_t)MAXN * D];        // pre-scaled GEMM output hs = (X@W)*dinv[row]
__device__ float g_agg[(size_t)MAXN * D];      // conv1 final output / BN input
__device__ float g_bnsums[2 * D];
__device__ int   g_bsum[NBLK];

// ---------------- packed f32x2 helpers ----------------
__device__ __forceinline__ unsigned long long pk2(float lo, float hi) {
    unsigned long long r;
    asm("mov.b64 %0, {%1, %2};" : "=l"(r) : "f"(lo), "f"(hi));
    return r;
}
__device__ __forceinline__ void upk2(unsigned long long v, float& lo, float& hi) {
    asm("mov.b64 {%0, %1}, %2;" : "=f"(lo), "=f"(hi) : "l"(v));
}
#define FFMA2(d, a, b) asm("fma.rn.f32x2 %0, %1, %2, %0;" : "+l"(d) : "l"(a), "l"(b))

// ---------------- init: zero deg + BN accumulators ----------------
__global__ void init_kernel(int n) {
    int i = blockIdx.x * blockDim.x + threadIdx.x;
    if (i < n) g_deg[i] = 0;
    if (i < 2 * D) g_bnsums[i] = 0.0f;
}

// ---------------- degree histogram over edge destinations ----------------
__global__ void deg_kernel(const int* __restrict__ dst, int E) {
    int e = blockIdx.x * blockDim.x + threadIdx.x;
    if (e < E) atomicAdd(&g_deg[dst[e]], 1);
}

// ---------------- block-level exclusive scan helpers ----------------
__device__ __forceinline__ int block_scan_excl(int v, int& total) {
    __shared__ int ws[8];
    int lane = threadIdx.x & 31, wid = threadIdx.x >> 5;
    int x = v;
#pragma unroll
    for (int o = 1; o < 32; o <<= 1) {
        int y = __shfl_up_sync(0xffffffffu, x, o);
        if (lane >= o) x += y;
    }
    if (lane == 31) ws[wid] = x;
    __syncthreads();
    if (wid == 0) {
        int t = (lane < 8) ? ws[lane] : 0;
#pragma unroll
        for (int o = 1; o < 8; o <<= 1) {
            int y = __shfl_up_sync(0xffffffffu, t, o);
            if (lane >= o) t += y;
        }
        if (lane < 8) ws[lane] = t;
    }
    __syncthreads();
    int incl = x + (wid > 0 ? ws[wid - 1] : 0);
    total = ws[7];
    return incl - v;
}

__global__ void scanA_kernel(int n) {
    int i = blockIdx.x * 256 + threadIdx.x;
    int v = (i < n) ? g_deg[i] : 0;
    int total;
    int excl = block_scan_excl(v, total);
    if (i < n) g_rowptr[i] = excl;
    if (threadIdx.x == 0) g_bsum[blockIdx.x] = total;
}

__global__ void scanB_kernel(int nb) {
    int i = threadIdx.x;
    int v = (i < nb) ? g_bsum[i] : 0;
    int total;
    int excl = block_scan_excl(v, total);
    if (i < nb) g_bsum[i] = excl;
}

__global__ void scanC_kernel(int n) {
    int i = blockIdx.x * 256 + threadIdx.x;
    if (i < n) {
        int rp = g_rowptr[i] + g_bsum[blockIdx.x];
        g_rowptr[i] = rp;
        g_cursor[i] = rp;
        g_dinv[i] = rsqrtf(1.0f + (float)g_deg[i]);
    }
}

// ---------------- bucket fill: csr[dst buckets] = src ----------------
__global__ void fill_kernel(const int* __restrict__ src, const int* __restrict__ dst, int E) {
    int e = blockIdx.x * blockDim.x + threadIdx.x;
    if (e < E) {
        int pos = atomicAdd(&g_cursor[dst[e]], 1);
        g_csr[pos] = src[e];
    }
}

// ---------------- GEMM: Hout = (X @ W) * dinv[row]  (BN+ReLU on X if asked)
__global__ __launch_bounds__(256, 2) void gemm_kernel(
    const float* __restrict__ X, const float* __restrict__ W,
    float* __restrict__ Hout, int n, int use_bn,
    const float* __restrict__ gamma, const float* __restrict__ beta,
    float invN)
{
    extern __shared__ float sm[];
    float* Ws      = sm;                 // 128*128
    float* Xs      = sm + D * D;         // 64*128
    float* scale_s = Xs + TM * D;        // 128
    float* shift_s = scale_s + D;        // 128

    int tid = threadIdx.x;
    int tx = tid & 31;      // column group (4 cols)
    int ty = tid >> 5;      // row group (8 rows)

    if (use_bn && tid < D) {
        float mu  = g_bnsums[tid] * invN;
        float var = g_bnsums[D + tid] * invN - mu * mu;
        float sc  = gamma[tid] * rsqrtf(var + 1e-5f);
        scale_s[tid] = sc;
        shift_s[tid] = beta[tid] - mu * sc;
    }

    const float4* W4 = (const float4*)W;
    float4* Ws4w = (float4*)Ws;
#pragma unroll
    for (int i = 0; i < 16; i++) Ws4w[tid + i * 256] = W4[tid + i * 256];
    __syncthreads();

    int row0 = blockIdx.x * TM;
    float4* Xs4w = (float4*)Xs;
#pragma unroll
    for (int i = 0; i < 8; i++) {
        int idx = tid + i * 256;
        int r   = idx >> 5;
        int c4  = idx & 31;
        int grow = row0 + r;
        float4 v = make_float4(0.f, 0.f, 0.f, 0.f);
        if (grow < n) v = ((const float4*)X)[(size_t)grow * 32 + c4];
        if (use_bn) {
            int f = c4 * 4;
            v.x = fmaxf(0.f, fmaf(v.x, scale_s[f + 0], shift_s[f + 0]));
            v.y = fmaxf(0.f, fmaf(v.y, scale_s[f + 1], shift_s[f + 1]));
            v.z = fmaxf(0.f, fmaf(v.z, scale_s[f + 2], shift_s[f + 2]));
            v.w = fmaxf(0.f, fmaf(v.w, scale_s[f + 3], shift_s[f + 3]));
        }
        Xs4w[idx] = v;
    }
    __syncthreads();

    const float4* Ws4 = (const float4*)Ws;
    const float4* Xs4 = (const float4*)Xs;

    // acc[rp][c] holds packed rows (2rp, 2rp+1) for output column tx*4+c
    unsigned long long acc[4][4];
#pragma unroll
    for (int rp = 0; rp < 4; rp++)
#pragma unroll
        for (int c = 0; c < 4; c++) acc[rp][c] = 0ull;

#pragma unroll 4
    for (int k4 = 0; k4 < 32; k4++) {
        float4 b0 = Ws4[(k4 * 4 + 0) * 32 + tx];
        float4 b1 = Ws4[(k4 * 4 + 1) * 32 + tx];
        float4 b2 = Ws4[(k4 * 4 + 2) * 32 + tx];
        float4 b3 = Ws4[(k4 * 4 + 3) * 32 + tx];
        unsigned long long bb0[4] = {pk2(b0.x,b0.x), pk2(b1.x,b1.x), pk2(b2.x,b2.x), pk2(b3.x,b3.x)};
        unsigned long long bb1[4] = {pk2(b0.y,b0.y), pk2(b1.y,b1.y), pk2(b2.y,b2.y), pk2(b3.y,b3.y)};
        unsigned long long bb2[4] = {pk2(b0.z,b0.z), pk2(b1.z,b1.z), pk2(b2.z,b2.z), pk2(b3.z,b3.z)};
        unsigned long long bb3[4] = {pk2(b0.w,b0.w), pk2(b1.w,b1.w), pk2(b2.w,b2.w), pk2(b3.w,b3.w)};
#pragma unroll
        for (int rp = 0; rp < 4; rp++) {
            float4 a0 = Xs4[(ty * 8 + rp * 2 + 0) * 32 + k4];
            float4 a1 = Xs4[(ty * 8 + rp * 2 + 1) * 32 + k4];
            unsigned long long ax = pk2(a0.x, a1.x);
            unsigned long long ay = pk2(a0.y, a1.y);
            unsigned long long az = pk2(a0.z, a1.z);
            unsigned long long aw = pk2(a0.w, a1.w);
            FFMA2(acc[rp][0], ax, bb0[0]); FFMA2(acc[rp][0], ay, bb0[1]);
            FFMA2(acc[rp][0], az, bb0[2]); FFMA2(acc[rp][0], aw, bb0[3]);
            FFMA2(acc[rp][1], ax, bb1[0]); FFMA2(acc[rp][1], ay, bb1[1]);
            FFMA2(acc[rp][1], az, bb1[2]); FFMA2(acc[rp][1], aw, bb1[3]);
            FFMA2(acc[rp][2], ax, bb2[0]); FFMA2(acc[rp][2], ay, bb2[1]);
            FFMA2(acc[rp][2], az, bb2[2]); FFMA2(acc[rp][2], aw, bb2[3]);
            FFMA2(acc[rp][3], ax, bb3[0]); FFMA2(acc[rp][3], ay, bb3[1]);
            FFMA2(acc[rp][3], az, bb3[2]); FFMA2(acc[rp][3], aw, bb3[3]);
        }
    }

#pragma unroll
    for (int rp = 0; rp < 4; rp++) {
        int r0 = row0 + ty * 8 + rp * 2;
        int r1 = r0 + 1;
        float4 h0, h1;
        upk2(acc[rp][0], h0.x, h1.x);
        upk2(acc[rp][1], h0.y, h1.y);
        upk2(acc[rp][2], h0.z, h1.z);
        upk2(acc[rp][3], h0.w, h1.w);
        if (r0 < n) {
            float dv = g_dinv[r0];
            h0.x *= dv; h0.y *= dv; h0.z *= dv; h0.w *= dv;
            *(float4*)(Hout + (size_t)r0 * D + tx * 4) = h0;
        }
        if (r1 < n) {
            float dv = g_dinv[r1];
            h1.x *= dv; h1.y *= dv; h1.z *= dv; h1.w *= dv;
            *(float4*)(Hout + (size_t)r1 * D + tx * 4) = h1;
        }
    }
}

// ---------------- CSR scatter: out[d] = (hs[d] + sum_{s in N(d)} hs[s]) * dinv[d] + bias
__global__ __launch_bounds__(256) void scatter_csr_kernel(
    const float* __restrict__ hs, float* __restrict__ out,
    const float* __restrict__ bias, int n)
{
    int node = (blockIdx.x * blockDim.x + threadIdx.x) >> 5;
    int lane = threadIdx.x & 31;
    if (node >= n) return;
    size_t base = (size_t)node * D + lane * 4;
    float4 acc = *(const float4*)(hs + base);   // self loop
    int start = g_rowptr[node];
    int cnt   = g_deg[node];
    int j = 0;
    for (; j + 4 <= cnt; j += 4) {
        int s0 = __ldg(&g_csr[start + j + 0]);
        int s1 = __ldg(&g_csr[start + j + 1]);
        int s2 = __ldg(&g_csr[start + j + 2]);
        int s3 = __ldg(&g_csr[start + j + 3]);
        float4 v0 = *(const float4*)(hs + (size_t)s0 * D + lane * 4);
        float4 v1 = *(const float4*)(hs + (size_t)s1 * D + lane * 4);
        float4 v2 = *(const float4*)(hs + (size_t)s2 * D + lane * 4);
        float4 v3 = *(const float4*)(hs + (size_t)s3 * D + lane * 4);
        acc.x += (v0.x + v1.x) + (v2.x + v3.x);
        acc.y += (v0.y + v1.y) + (v2.y + v3.y);
        acc.z += (v0.z + v1.z) + (v2.z + v3.z);
        acc.w += (v0.w + v1.w) + (v2.w + v3.w);
    }
    for (; j < cnt; j++) {
        int s = __ldg(&g_csr[start + j]);
        float4 v = *(const float4*)(hs + (size_t)s * D + lane * 4);
        acc.x += v.x; acc.y += v.y; acc.z += v.z; acc.w += v.w;
    }
    float dv = g_dinv[node];
    float4 bv = ((const float4*)bias)[lane];
    float4 o;
    o.x = fmaf(acc.x, dv, bv.x);
    o.y = fmaf(acc.y, dv, bv.y);
    o.z = fmaf(acc.z, dv, bv.z);
    o.w = fmaf(acc.w, dv, bv.w);
    *(float4*)(out + base) = o;
}

// ---------------- BN statistics ----------------
__global__ __launch_bounds__(512) void bnstat_kernel(const float* __restrict__ agg, int n) {
    int f = threadIdx.x & (D - 1);
    int g = threadIdx.x >> 7;
    int r0 = blockIdx.x * 512 + g;
    int rend = min(n, (int)(blockIdx.x * 512 + 512));
    float s = 0.f, s2 = 0.f;
    for (int r = r0; r < rend; r += 4) {
        float v = agg[(size_t)r * D + f];
        s += v;
        s2 = fmaf(v, v, s2);
    }
    atomicAdd(&g_bnsums[f], s);
    atomicAdd(&g_bnsums[D + f], s2);
}

extern "C" void kernel_launch(void* const* d_in, const int* in_sizes, int n_in,
                              void* d_out, int out_size)
{
    const float* x     = (const float*)d_in[0];
    const int*   ei    = (const int*)  d_in[1];
    const float* W1    = (const float*)d_in[2];
    const float* b1    = (const float*)d_in[3];
    const float* gamma = (const float*)d_in[4];
    const float* beta  = (const float*)d_in[5];
    const float* W2    = (const float*)d_in[6];
    const float* b2    = (const float*)d_in[7];
    float* out = (float*)d_out;

    int n = in_sizes[0] / D;
    int E = in_sizes[1] / 2;
    const int* src = ei;
    const int* dst = ei + E;
    float invN = 1.0f / (float)n;

    int smem = (D * D + TM * D + 2 * D) * (int)sizeof(float);  // 99328 B
    cudaFuncSetAttribute(gemm_kernel,
                         cudaFuncAttributeMaxDynamicSharedMemorySize, smem);

    void* p;
    cudaGetSymbolAddress(&p, g_h);   float* hbuf   = (float*)p;
    cudaGetSymbolAddress(&p, g_agg); float* aggbuf = (float*)p;

    int nb = (n + 255) / 256;

    init_kernel<<<nb, 256>>>(n);
    deg_kernel<<<(E + 255) / 256, 256>>>(dst, E);
    scanA_kernel<<<nb, 256>>>(n);
    scanB_kernel<<<1, 256>>>(nb);
    scanC_kernel<<<nb, 256>>>(n);
    fill_kernel<<<(E + 255) / 256, 256>>>(src, dst, E);

    int gblocks = (n + TM - 1) / TM;
    int sblocks = (n * 32 + 255) / 256;

    // conv1
    gemm_kernel<<<gblocks, 256, smem>>>(x, W1, hbuf, n, 0, nullptr, nullptr, invN);
    scatter_csr_kernel<<<sblocks, 256>>>(hbuf, aggbuf, b1, n);

    // BN stats over conv1 output
    bnstat_kernel<<<(n + 511) / 512, 512>>>(aggbuf, n);

    // conv2 (BN+ReLU fused into X load)
    gemm_kernel<<<gblocks, 256, smem>>>(aggbuf, W2, hbuf, n, 1, gamma, beta, invN);
    scatter_csr_kernel<<<sblocks, 256>>>(hbuf, out, b2, n);
}